// round 2
// baseline (speedup 1.0000x reference)
#include <cuda_runtime.h>
#include <cuda_bf16.h>
#include <math.h>

#define C_CH   128
#define HW     3136          // 56*56
#define B_SZ   64
#define NCHUNK 8
#define NTOT   (B_SZ * HW)   // 200704 elements per channel
#define HW4    (HW / 4)      // 784 float4 per (b,c) plane

// scratch (no device allocation allowed)
__device__ float g_max [C_CH * NCHUNK];
__device__ float g_min [C_CH * NCHUNK];
__device__ float g_sum [C_CH * NCHUNK];
__device__ float g_avg [C_CH];
__device__ float g_scale[C_CH];

__device__ __forceinline__ float qbf(float v) {
    // bf16 round-to-nearest-even round trip == jnp astype(bf16).astype(f32)
    return __bfloat162float(__float2bfloat16(v));
}

// ---------------------------------------------------------------------------
// Pass 1: per (channel, chunk) max / min / sum over 8 batches * HW elements.
// chunk k covers batches [8k, 8k+8) because chunk_size = 8*H*W in the
// channel-major flatten of the reference.
// ---------------------------------------------------------------------------
__global__ void __launch_bounds__(256) stats_kernel(const float* __restrict__ x) {
    const int c = blockIdx.x;    // 0..127
    const int k = blockIdx.y;    // 0..7
    const int tid = threadIdx.x;

    float vmax = -INFINITY, vmin = INFINITY, vsum = 0.0f;

    #pragma unroll
    for (int j = 0; j < 8; ++j) {
        const int b = 8 * k + j;
        const float4* p = reinterpret_cast<const float4*>(
            x + ((size_t)b * C_CH + c) * HW);
        for (int i = tid; i < HW4; i += 256) {
            float4 v = p[i];
            float a0 = qbf(v.x), a1 = qbf(v.y), a2 = qbf(v.z), a3 = qbf(v.w);
            vmax = fmaxf(vmax, fmaxf(fmaxf(a0, a1), fmaxf(a2, a3)));
            vmin = fminf(vmin, fminf(fminf(a0, a1), fminf(a2, a3)));
            vsum += (a0 + a1) + (a2 + a3);
        }
    }

    // warp reduce
    #pragma unroll
    for (int o = 16; o > 0; o >>= 1) {
        vmax = fmaxf(vmax, __shfl_down_sync(0xFFFFFFFFu, vmax, o));
        vmin = fminf(vmin, __shfl_down_sync(0xFFFFFFFFu, vmin, o));
        vsum +=            __shfl_down_sync(0xFFFFFFFFu, vsum, o);
    }

    __shared__ float smax[8], smin[8], ssum[8];
    const int wid  = tid >> 5;
    const int lane = tid & 31;
    if (lane == 0) { smax[wid] = vmax; smin[wid] = vmin; ssum[wid] = vsum; }
    __syncthreads();

    if (tid == 0) {
        float m = smax[0], n = smin[0], s = ssum[0];
        #pragma unroll
        for (int w = 1; w < 8; ++w) {
            m = fmaxf(m, smax[w]);
            n = fminf(n, smin[w]);
            s += ssum[w];
        }
        g_max[c * NCHUNK + k] = m;
        g_min[c * NCHUNK + k] = n;
        g_sum[c * NCHUNK + k] = s;
    }
}

// ---------------------------------------------------------------------------
// Pass 2: per-channel scalars, following the reference's quantization order.
// ---------------------------------------------------------------------------
__global__ void finalize_kernel() {
    const int c = threadIdx.x;   // 1 block, 128 threads
    if (c >= C_CH) return;

    float sm = 0.f, sn = 0.f, st = 0.f;
    #pragma unroll
    for (int k = 0; k < NCHUNK; ++k) {
        sm += g_max[c * NCHUNK + k];
        sn += g_min[c * NCHUNK + k];
        st += g_sum[c * NCHUNK + k];
    }
    const float sum_max = qbf(sm);
    const float sum_min = qbf(sn);
    const float avg_max = qbf(sum_max / (float)NCHUNK);
    const float avg_min = qbf(sum_min / (float)NCHUNK);
    const float total   = qbf(st);
    const float avg     = qbf(total / (float)NTOT);

    const double chunk_size = (double)(NCHUNK * HW);  // 25088
    const float scale_fix = (float)(1.0 / sqrt(2.0 * log(chunk_size)));
    const float scale = qbf(1.0f / ((avg_max - avg_min) * scale_fix + 1e-5f));

    g_avg[c]   = avg;
    g_scale[c] = scale;
}

// ---------------------------------------------------------------------------
// Pass 3: out = q( q((q(x) - avg) * scale) * q(gamma) + beta )
// one block per (b, c) plane: 784 float4 per block.
// ---------------------------------------------------------------------------
__global__ void __launch_bounds__(256) norm_kernel(const float* __restrict__ x,
                                                   const float* __restrict__ gamma,
                                                   const float* __restrict__ beta,
                                                   float* __restrict__ out) {
    const int bc = blockIdx.x;          // b*C + c
    const int c  = bc & (C_CH - 1);

    const float avg   = g_avg[c];
    const float scale = g_scale[c];
    const float g     = qbf(gamma[c]);
    const float be    = beta[c];

    const float4* px = reinterpret_cast<const float4*>(x)   + (size_t)bc * HW4;
    float4*       po = reinterpret_cast<float4*>(out)        + (size_t)bc * HW4;

    for (int i = threadIdx.x; i < HW4; i += 256) {
        float4 v = px[i];
        float4 r;
        float t;
        t = qbf((qbf(v.x) - avg) * scale); r.x = qbf(t * g + be);
        t = qbf((qbf(v.y) - avg) * scale); r.y = qbf(t * g + be);
        t = qbf((qbf(v.z) - avg) * scale); r.z = qbf(t * g + be);
        t = qbf((qbf(v.w) - avg) * scale); r.w = qbf(t * g + be);
        po[i] = r;
    }
}

// ---------------------------------------------------------------------------
extern "C" void kernel_launch(void* const* d_in, const int* in_sizes, int n_in,
                              void* d_out, int out_size) {
    const float* x     = (const float*)d_in[0];
    const float* gamma = (const float*)d_in[1];
    const float* beta  = (const float*)d_in[2];
    // d_in[3] = num_chunks (always 8 for this problem's fixed shapes)
    float* out = (float*)d_out;

    dim3 grid1(C_CH, NCHUNK);
    stats_kernel<<<grid1, 256>>>(x);
    finalize_kernel<<<1, C_CH>>>();
    norm_kernel<<<B_SZ * C_CH, 256>>>(x, gamma, beta, out);
}